// round 4
// baseline (speedup 1.0000x reference)
#include <cuda_runtime.h>

#define NQ    12
#define DIM   4096
#define NL    4
#define NTH   256                          // threads per batch element (half-CTA)
#define NT    512                          // threads per CTA (2 batch elements)
#define KPT   16                           // amplitudes per thread (4 local qubits)
#define SW(i) ((i) ^ (((i) >> 4) & 0xF))   // bank-conflict swizzle

typedef unsigned long long u64;

struct cplx { float x, y; };

__device__ __forceinline__ cplx cmul(cplx a, cplx b) {
    return { a.x*b.x - a.y*b.y, a.x*b.y + a.y*b.x };
}
__device__ __forceinline__ cplx cadd(cplx a, cplx b) {
    return { a.x + b.x, a.y + b.y };
}
__device__ __forceinline__ void mmul(const cplx* A, const cplx* B, cplx* C) {
    C[0] = cadd(cmul(A[0], B[0]), cmul(A[1], B[2]));
    C[1] = cadd(cmul(A[0], B[1]), cmul(A[1], B[3]));
    C[2] = cadd(cmul(A[2], B[0]), cmul(A[3], B[2]));
    C[3] = cadd(cmul(A[2], B[1]), cmul(A[3], B[3]));
}

// ---- packed f32x2 helpers ----
__device__ __forceinline__ u64 mul2(u64 a, u64 b) {
    u64 d; asm("mul.rn.f32x2 %0, %1, %2;" : "=l"(d) : "l"(a), "l"(b)); return d;
}
__device__ __forceinline__ u64 fma2(u64 a, u64 b, u64 c) {
    u64 d; asm("fma.rn.f32x2 %0, %1, %2, %3;" : "=l"(d) : "l"(a), "l"(b), "l"(c)); return d;
}
__device__ __forceinline__ u64 swp(u64 a) {   // (x,y) -> (y,x)
    u64 d;
    asm("{\n\t.reg .b32 lo, hi;\n\tmov.b64 {lo, hi}, %1;\n\tmov.b64 %0, {hi, lo};\n\t}"
        : "=l"(d) : "l"(a));
    return d;
}
__device__ __forceinline__ u64 pk(float lo, float hi) {
    union { float2 f; u64 u; } c; c.f = make_float2(lo, hi); return c.u;
}

// per-half barrier: half 0 -> bar 1, half 1 -> bar 2, each over 256 threads
__device__ __forceinline__ void hbar(int half) {
    asm volatile("bar.sync %0, %1;" :: "r"(half + 1), "r"(NTH) : "memory");
}

// Apply 2x2 complex gate (packed constants up[8]) on local register bit m of v[16].
__device__ __forceinline__ void apply_level(u64 v[KPT], const u64* __restrict__ up, int m) {
    const u64 a00 = up[0], b00 = up[1], a01 = up[2], b01 = up[3];
    const u64 a10 = up[4], b10 = up[5], a11 = up[6], b11 = up[7];
    #pragma unroll
    for (int h = 0; h < 8; h++) {
        const int k0 = ((h >> m) << (m + 1)) | (h & ((1 << m) - 1));
        const int k1 = k0 | (1 << m);
        const u64 s0  = v[k0];
        const u64 s1  = v[k1];
        const u64 s0s = swp(s0);
        const u64 s1s = swp(s1);
        v[k0] = fma2(b01, s1s, fma2(a01, s1, fma2(b00, s0s, mul2(a00, s0))));
        v[k1] = fma2(b11, s1s, fma2(a11, s1, fma2(b10, s0s, mul2(a10, s0))));
    }
}

extern __shared__ u64 smem_raw[];

__global__ __launch_bounds__(NT, 1)
void qsim_kernel(const float* __restrict__ x,
                 const float* __restrict__ params,
                 float* __restrict__ out)
{
    const int tid  = threadIdx.x;
    const int half = tid >> 8;          // 0 or 1: which batch element
    const int t    = tid & 0xFF;        // lane within the half (0..255)
    const int b    = blockIdx.x * 2 + half;

    // smem layout: st[2][DIM] | Upk[2][NL*NQ*8] | red[2][8]
    u64*   st  = smem_raw + half * DIM;
    u64*   Upk = smem_raw + 2 * DIM + half * (NL * NQ * 8);
    float* red = (float*)(smem_raw + 2 * DIM + 2 * (NL * NQ * 8)) + half * 8;

    // ---- build 48 fused gate matrices for this half's batch element ----
    if (t < NL * NQ) {
        const int l = t / NQ;
        const int q = t % NQ;
        const float xv = x[b];
        const float x1 = asinf(xv);
        const float x2 = acosf(xv * xv);

        float c, s;
        sincosf(0.5f * x1, &s, &c);
        cplx RY[4]  = { {c,0.f}, {-s,0.f}, {s,0.f}, {c,0.f} };
        sincosf(0.5f * x2, &s, &c);
        cplx RZ[4]  = { {c,-s}, {0.f,0.f}, {0.f,0.f}, {c,s} };

        const float t0 = params[q * (NL * 3) + l * 3 + 0];
        const float t1 = params[q * (NL * 3) + l * 3 + 1];
        const float t2 = params[q * (NL * 3) + l * 3 + 2];

        sincosf(0.5f * t0, &s, &c);
        cplx RX0[4] = { {c,0.f}, {0.f,-s}, {0.f,-s}, {c,0.f} };
        sincosf(0.5f * t1, &s, &c);
        cplx RZ1[4] = { {c,-s}, {0.f,0.f}, {0.f,0.f}, {c,s} };
        sincosf(0.5f * t2, &s, &c);
        cplx RX2[4] = { {c,0.f}, {0.f,-s}, {0.f,-s}, {c,0.f} };

        cplx A[4], B[4];
        mmul(RZ,  RY, A);
        mmul(RX0, A,  B);
        mmul(RZ1, B,  A);
        mmul(RX2, A,  B);
        #pragma unroll
        for (int m = 0; m < 4; m++) {
            Upk[(l * NQ + q) * 8 + 2*m]     = pk(B[m].x, B[m].x);
            Upk[(l * NQ + q) * 8 + 2*m + 1] = pk(-B[m].y, B[m].y);
        }
    }
    hbar(half);

    u64 v[KPT];

    for (int l = 0; l < NL; l++) {
        const u64* Ul = Upk + l * NQ * 8;

        // ======== pass 0: local bits 11..8 (qubits 3..0) ========
        if (l == 0) {
            #pragma unroll
            for (int k = 0; k < KPT; k++) v[k] = 0ull;
            if (t == 0) v[0] = pk(1.f, 0.f);
        } else {
            // fold previous layer's CNOT chain: new[i] = old[i ^ (i>>1)]
            #pragma unroll
            for (int k = 0; k < KPT; k++) {
                const int i = (k << 8) | t;
                const int j = i ^ (i >> 1);
                v[k] = st[SW(j)];
            }
            hbar(half);
        }
        #pragma unroll
        for (int m = 0; m < 4; m++) apply_level(v, Ul + (3 - m) * 8, m);
        #pragma unroll
        for (int k = 0; k < KPT; k++) st[SW((k << 8) | t)] = v[k];
        hbar(half);

        // ======== pass 1: local bits 7..4 (qubits 7..4) ========
        {
            const int base = ((t & 0xF0) << 4) | (t & 0x0F);
            #pragma unroll
            for (int k = 0; k < KPT; k++) v[k] = st[SW(base | (k << 4))];
            #pragma unroll
            for (int m = 0; m < 4; m++) apply_level(v, Ul + (7 - m) * 8, m);
            #pragma unroll
            for (int k = 0; k < KPT; k++) st[SW(base | (k << 4))] = v[k];
            hbar(half);
        }

        // ======== pass 2: local bits 3..0 (qubits 11..8) ========
        {
            const int base = t << 4;
            #pragma unroll
            for (int k = 0; k < KPT; k++) v[k] = st[SW(base | k)];
            #pragma unroll
            for (int m = 0; m < 4; m++) apply_level(v, Ul + (11 - m) * 8, m);
            if (l < NL - 1) {
                #pragma unroll
                for (int k = 0; k < KPT; k++) st[SW(base | k)] = v[k];
                hbar(half);
            }
            // last layer: stay in registers; CNOT perm preserves bit 11.
        }
    }

    // ---- <Z_0>: sign = bit 11 of i = (t<<4)|k -> bit 7 of t ----
    float acc = 0.f;
    #pragma unroll
    for (int k = 0; k < KPT; k++) {
        union { u64 u; float2 f; } c; c.u = v[k];
        acc += c.f.x * c.f.x + c.f.y * c.f.y;
    }
    acc = (t & 0x80) ? -acc : acc;

    #pragma unroll
    for (int o = 16; o > 0; o >>= 1) acc += __shfl_xor_sync(0xffffffffu, acc, o);
    if ((t & 31) == 0) red[t >> 5] = acc;
    hbar(half);
    if (t < 32) {
        float v2 = (t < 8) ? red[t] : 0.f;
        #pragma unroll
        for (int o = 4; o > 0; o >>= 1) v2 += __shfl_xor_sync(0xffffffffu, v2, o);
        if (t == 0) out[b] = v2;
    }
}

extern "C" void kernel_launch(void* const* d_in, const int* in_sizes, int n_in,
                              void* d_out, int out_size)
{
    const float* x      = (const float*)d_in[0];
    const float* params = (const float*)d_in[1];
    if (n_in >= 2 && in_sizes[0] != 256 && in_sizes[1] == 256) {
        x      = (const float*)d_in[1];
        params = (const float*)d_in[0];
    }
    float* out = (float*)d_out;

    // smem: 2*DIM u64 + 2*(NL*NQ*8) u64 + 16 floats
    const size_t smem = (size_t)(2 * DIM + 2 * (NL * NQ * 8)) * sizeof(u64) + 64;
    static bool attr_set = false;
    if (!attr_set) {
        cudaFuncSetAttribute(qsim_kernel, cudaFuncAttributeMaxDynamicSharedMemorySize,
                             (int)smem);
        attr_set = true;
    }
    qsim_kernel<<<128, NT, smem>>>(x, params, out);
}

// round 5
// speedup vs baseline: 1.2791x; 1.2791x over previous
#include <cuda_runtime.h>

#define NQ    12
#define DIM   4096
#define NL    4
#define NT    256
#define KPT   16
#define SW(i) ((i) ^ (((i) >> 4) & 0xF))   // bank-conflict swizzle

struct cplx { float x, y; };

__device__ __forceinline__ cplx cmul(cplx a, cplx b) {
    return { a.x*b.x - a.y*b.y, a.x*b.y + a.y*b.x };
}
__device__ __forceinline__ cplx cadd(cplx a, cplx b) {
    return { a.x + b.x, a.y + b.y };
}
__device__ __forceinline__ void mmul(const cplx* A, const cplx* B, cplx* C) {
    C[0] = cadd(cmul(A[0], B[0]), cmul(A[1], B[2]));
    C[1] = cadd(cmul(A[0], B[1]), cmul(A[1], B[3]));
    C[2] = cadd(cmul(A[2], B[0]), cmul(A[3], B[2]));
    C[3] = cadd(cmul(A[2], B[1]), cmul(A[3], B[3]));
}

// real RY rotation on local register bit m: r0 = c*s0 - s*s1 ; r1 = s*s0 + c*s1
__device__ __forceinline__ void apply_ry(float2 v[KPT], float c, float s, int m) {
    #pragma unroll
    for (int h = 0; h < 8; h++) {
        const int k0 = ((h >> m) << (m + 1)) | (h & ((1 << m) - 1));
        const int k1 = k0 | (1 << m);
        const float2 s0 = v[k0];
        const float2 s1 = v[k1];
        v[k0].x = c*s0.x - s*s1.x;
        v[k0].y = c*s0.y - s*s1.y;
        v[k1].x = s*s0.x + c*s1.x;
        v[k1].y = s*s0.y + c*s1.y;
    }
}

__global__ __launch_bounds__(NT, 2)
void qsim_kernel(const float* __restrict__ x,
                 const float* __restrict__ params,
                 float* __restrict__ out)
{
    __shared__ float2 st[DIM];                 // 32 KB state (swizzled)
    __shared__ float2 Dg[NL][3][16];           // fused gamma-diagonals per pass
    __shared__ float2 Da[NL][3][16];           // fused alpha-diagonals per pass
    __shared__ float2 RYcs[NL][NQ];            // (cos, sin) of RY theta/2
    __shared__ float2 EG[NL][NQ], EA[NL][NQ];  // per-qubit e^{-i gamma/2}, e^{-i alpha/2}
    __shared__ float2 Uc0[8][2];               // fused-U column 0 for layer0 qubits 0..7
    __shared__ float  red[NT / 32];

    const int t = threadIdx.x;
    const int b = blockIdx.x;

    // ---- phase 1: build 48 fused gates + ZYZ decomposition ----
    if (t < NL * NQ) {
        const int l = t / NQ;
        const int q = t % NQ;
        const float xv = x[b];
        const float x1 = asinf(xv);
        const float x2 = acosf(xv * xv);

        float c, s;
        sincosf(0.5f * x1, &s, &c);
        cplx RY[4]  = { {c,0.f}, {-s,0.f}, {s,0.f}, {c,0.f} };
        sincosf(0.5f * x2, &s, &c);
        cplx RZ[4]  = { {c,-s}, {0.f,0.f}, {0.f,0.f}, {c,s} };

        const float t0 = params[q * (NL * 3) + l * 3 + 0];
        const float t1 = params[q * (NL * 3) + l * 3 + 1];
        const float t2 = params[q * (NL * 3) + l * 3 + 2];

        sincosf(0.5f * t0, &s, &c);
        cplx RX0[4] = { {c,0.f}, {0.f,-s}, {0.f,-s}, {c,0.f} };
        sincosf(0.5f * t1, &s, &c);
        cplx RZ1[4] = { {c,-s}, {0.f,0.f}, {0.f,0.f}, {c,s} };
        sincosf(0.5f * t2, &s, &c);
        cplx RX2[4] = { {c,0.f}, {0.f,-s}, {0.f,-s}, {c,0.f} };

        cplx A[4], B[4];
        mmul(RZ,  RY, A);
        mmul(RX0, A,  B);
        mmul(RZ1, B,  A);
        mmul(RX2, A,  B);   // fused U, SU(2)

        if (l == 0 && q < 8) {      // layer-0 fast path uses full column 0
            Uc0[q][0] = make_float2(B[0].x, B[0].y);   // u00
            Uc0[q][1] = make_float2(B[2].x, B[2].y);   // u10
        }
        // ZYZ: U = RZ(alpha) RY(theta) RZ(gamma)
        const float cc = sqrtf(B[0].x*B[0].x + B[0].y*B[0].y);   // cos(theta/2)
        const float ss = sqrtf(B[2].x*B[2].x + B[2].y*B[2].y);   // sin(theta/2)
        RYcs[l][q] = make_float2(cc, ss);
        const float aa = atan2f(-B[0].y, B[0].x);   // (alpha+gamma)/2
        const float bb = atan2f( B[2].y, B[2].x);   // (alpha-gamma)/2
        float sg, cg, sa, ca;
        sincosf(0.5f * (aa - bb), &sg, &cg);        // gamma/2
        sincosf(0.5f * (aa + bb), &sa, &ca);        // alpha/2
        EG[l][q] = make_float2(cg, -sg);            // e^{-i gamma/2}
        EA[l][q] = make_float2(ca, -sa);            // e^{-i alpha/2}
    }
    __syncthreads();

    // ---- phase 2: build 16-entry fused diagonal tables per (layer, pass) ----
    if (t < NL * 3 * 16) {
        const int l = t / 48;
        const int r = t % 48;
        const int p = r / 16;
        const int k = r % 16;
        cplx g = {1.f, 0.f}, a2 = {1.f, 0.f};
        #pragma unroll
        for (int m = 0; m < 4; m++) {
            const int q = 4 * p + 3 - m;            // bit m of k <-> qubit q
            float2 e = EG[l][q];
            if ((k >> m) & 1) e.y = -e.y;           // conj for bit=1
            g = cmul(g, cplx{e.x, e.y});
            e = EA[l][q];
            if ((k >> m) & 1) e.y = -e.y;
            a2 = cmul(a2, cplx{e.x, e.y});
        }
        Dg[l][p][k] = make_float2(g.x, g.y);
        Da[l][p][k] = make_float2(a2.x, a2.y);
    }
    __syncthreads();

    float2 v[KPT];

    // pass body: gamma-diag, 4 real RYs, alpha-diag
    #define PASS_BODY(L, P)                                                   \
        {                                                                     \
            _Pragma("unroll")                                                 \
            for (int k = 0; k < KPT; k++) {                                   \
                const float2 d = Dg[L][P][k];                                 \
                const float2 s0 = v[k];                                       \
                v[k].x = d.x*s0.x - d.y*s0.y;                                 \
                v[k].y = d.x*s0.y + d.y*s0.x;                                 \
            }                                                                 \
            _Pragma("unroll")                                                 \
            for (int m = 0; m < 4; m++) {                                     \
                const float2 cs = RYcs[L][4*(P) + 3 - m];                     \
                apply_ry(v, cs.x, cs.y, m);                                   \
            }                                                                 \
            _Pragma("unroll")                                                 \
            for (int k = 0; k < KPT; k++) {                                   \
                const float2 d = Da[L][P][k];                                 \
                const float2 s0 = v[k];                                       \
                v[k].x = d.x*s0.x - d.y*s0.y;                                 \
                v[k].y = d.x*s0.y + d.y*s0.x;                                 \
            }                                                                 \
        }

    // ======== layer 0: passes 0+1 collapse to a Kronecker column ========
    {
        cplx w = {1.f, 0.f};
        #pragma unroll
        for (int q = 0; q < 8; q++) {
            const float2 e = ((t >> (7 - q)) & 1) ? Uc0[q][1] : Uc0[q][0];
            w = cmul(w, cplx{e.x, e.y});
        }
        v[0] = make_float2(w.x, w.y);
        #pragma unroll
        for (int k = 1; k < KPT; k++) v[k] = make_float2(0.f, 0.f);

        PASS_BODY(0, 2)                         // qubits 8..11 on bits 3..0
        const int base = t << 4;
        #pragma unroll
        for (int k = 0; k < KPT; k++) st[SW(base | k)] = v[k];
        __syncthreads();
    }

    // ======== layers 1..3 ========
    for (int l = 1; l < NL; l++) {
        // pass 0 (bits 11..8), folding previous layer's CNOT chain i^(i>>1)
        #pragma unroll
        for (int k = 0; k < KPT; k++) {
            const int i = (k << 8) | t;
            const int j = i ^ (i >> 1);
            v[k] = st[SW(j)];
        }
        __syncthreads();
        PASS_BODY(l, 0)
        #pragma unroll
        for (int k = 0; k < KPT; k++) st[SW((k << 8) | t)] = v[k];
        __syncthreads();

        // pass 1 (bits 7..4)
        {
            const int base = ((t & 0xF0) << 4) | (t & 0x0F);
            #pragma unroll
            for (int k = 0; k < KPT; k++) v[k] = st[SW(base | (k << 4))];
            PASS_BODY(l, 1)
            #pragma unroll
            for (int k = 0; k < KPT; k++) st[SW(base | (k << 4))] = v[k];
            __syncthreads();
        }

        // pass 2 (bits 3..0)
        {
            const int base = t << 4;
            #pragma unroll
            for (int k = 0; k < KPT; k++) v[k] = st[SW(base | k)];
            PASS_BODY(l, 2)
            if (l < NL - 1) {
                #pragma unroll
                for (int k = 0; k < KPT; k++) st[SW(base | k)] = v[k];
                __syncthreads();
            }
            // last layer: stay in registers; CNOT perm preserves bit 11.
        }
    }

    // ---- <Z_0>: sign = bit 11 of i = (t<<4)|k -> bit 7 of t ----
    float acc = 0.f;
    #pragma unroll
    for (int k = 0; k < KPT; k++)
        acc += v[k].x * v[k].x + v[k].y * v[k].y;
    acc = (t & 0x80) ? -acc : acc;

    #pragma unroll
    for (int o = 16; o > 0; o >>= 1) acc += __shfl_xor_sync(0xffffffffu, acc, o);
    if ((t & 31) == 0) red[t >> 5] = acc;
    __syncthreads();
    if (t < 32) {
        float v2 = (t < NT / 32) ? red[t] : 0.f;
        #pragma unroll
        for (int o = 4; o > 0; o >>= 1) v2 += __shfl_xor_sync(0xffffffffu, v2, o);
        if (t == 0) out[b] = v2;
    }
}

extern "C" void kernel_launch(void* const* d_in, const int* in_sizes, int n_in,
                              void* d_out, int out_size)
{
    const float* x      = (const float*)d_in[0];
    const float* params = (const float*)d_in[1];
    if (n_in >= 2 && in_sizes[0] != 256 && in_sizes[1] == 256) {
        x      = (const float*)d_in[1];
        params = (const float*)d_in[0];
    }
    float* out = (float*)d_out;
    qsim_kernel<<<256, NT>>>(x, params, out);
}